// round 12
// baseline (speedup 1.0000x reference)
#include <cuda_runtime.h>
#include <cstdint>

// Angles2Backbone: per-batch sequential product of 3L NeRF extension matrices,
// parallelized as a block-level affine-matrix scan:
//   phase 1: per-thread chunk product (12 matrices), specialized omega step
//            and direct-M init; captures per-step local translations tau_s
//   phase 1.5: invalid-chunk threads stream zeros NOW (overlaps the scan)
//   phase 2a: warp-shuffle inclusive scan (skipped for fully-invalid warps)
//   phase 2b: ONE barrier; every active warp redundantly scans the 16 warp
//             totals in its own lanes and shuffles out its exclusive prefix
//   phase 3: pos[t] = R_prefix * tau_s + t_prefix, float4 stores
//
// angles_length dtype: the reference asks JAX for int64, but default JAX
// (x64 disabled) silently produces int32. We auto-detect: an int64 array of
// values in [1, 2^31) has all odd 32-bit words == 0; an int32 array of
// values >= 1 does not. Deterministic given the input bytes.
//
// Shapes: input [B,2,L] f32, angles_length [B] i32|i64, out [B, 9L] f32.
// B=256, L=2048 -> 3L=6144 = 512 threads * 12 steps.

#define THREADS 512
#define NWARPS  16
#define STEPS   12      // matrices per thread (3 per residue)
#define RESID   4       // residues per thread

// ---------------------------------------------------------------------------
// FMA-only sincos for x in [-pi, pi]: quadrant reduction + deg-7/8 Taylor on
// [-pi/4, pi/4]; abs err < 1e-6. Avoids the MUFU pipe entirely.
// ---------------------------------------------------------------------------
__device__ __forceinline__ void sincos_fast(float x, float& s, float& c) {
    const float TWO_OVER_PI = 0.6366197723675814f;
    const float PIO2        = 1.5707963267948966f;
    float q = rintf(x * TWO_OVER_PI);
    int  iq = (int)q;
    float r  = fmaf(q, -PIO2, x);
    float r2 = r * r;
    float sp = fmaf(r2, fmaf(r2, fmaf(r2, -1.9841270e-4f, 8.3333338e-3f),
                             -1.6666667e-1f), 1.0f);
    float sr = r * sp;
    float cr = fmaf(r2, fmaf(r2, fmaf(r2, fmaf(r2, 2.4801587e-5f,
                             -1.3888889e-3f), 4.1666668e-2f), -0.5f), 1.0f);
    int m = iq & 3;
    bool swap = (m & 1);
    float ss = swap ? cr : sr;
    float cc = swap ? sr : cr;
    if (m & 2)        ss = -ss;
    if ((m + 1) & 2)  cc = -cc;
    s = ss;
    c = cc;
}

// ---------------------------------------------------------------------------
// Affine 3x4, column-major: A[0..2]=col0, A[3..5]=col1, A[6..8]=col2,
// A[9..11]=translation.  A <- A * M(ca,sa,R,ct,st), where M columns:
// col0=(-ca, sa*ct, sa*st), col1=(-sa, -ca*ct, -ca*st), col2=(0,-st,ct),
// trans = R*col0.
// ---------------------------------------------------------------------------
__device__ __forceinline__ void stepmul(float* A, float ca, float sa, float R,
                                        float ct, float st) {
    float m10 = sa * ct, m20 = sa * st;
    float m11 = -ca * ct, m21 = -ca * st;
    float c0[3], c1[3], c2[3];
#pragma unroll
    for (int r = 0; r < 3; r++) {
        c0[r] = fmaf(A[r], -ca, fmaf(A[3 + r], m10, A[6 + r] * m20));
        c1[r] = fmaf(A[r], -sa, fmaf(A[3 + r], m11, A[6 + r] * m21));
        c2[r] = fmaf(A[3 + r], -st, A[6 + r] * ct);
    }
#pragma unroll
    for (int r = 0; r < 3; r++) {
        A[9 + r] = fmaf(R, c0[r], A[9 + r]);
        A[r]     = c0[r];
        A[3 + r] = c1[r];
        A[6 + r] = c2[r];
    }
}

// Omega step: ct=-1, st=0 -> M cols: col0=(-ca,-sa,0), col1=(-sa,ca,0),
// col2=(0,0,-1), trans=R*col0.  ~half the ops of the generic stepmul.
__device__ __forceinline__ void stepmul_omega(float* A, float ca, float sa,
                                              float R) {
#pragma unroll
    for (int r = 0; r < 3; r++) {
        float c0 = fmaf(A[r], -ca, A[3 + r] * -sa);
        float c1 = fmaf(A[r], -sa, A[3 + r] *  ca);
        float c2 = -A[6 + r];
        A[9 + r] = fmaf(R, c0, A[9 + r]);
        A[r]     = c0;
        A[3 + r] = c1;
        A[6 + r] = c2;
    }
}

// A = M(ca,sa,R,ct,st) directly (first step applied to identity).
__device__ __forceinline__ void set_from_M(float* A, float ca, float sa,
                                           float R, float ct, float st) {
    A[0] = -ca;      A[1] = sa * ct;  A[2] = sa * st;
    A[3] = -sa;      A[4] = -ca * ct; A[5] = -ca * st;
    A[6] = 0.f;      A[7] = -st;      A[8] = ct;
    A[9] = R * A[0]; A[10] = R * A[1]; A[11] = R * A[2];
}

__device__ __forceinline__ void set_identity(float* A) {
#pragma unroll
    for (int k = 0; k < 12; k++) A[k] = 0.f;
    A[0] = 1.f; A[4] = 1.f; A[8] = 1.f;
}

// C = P * A  (P is the earlier/left prefix) -- plain scalar FMA version.
__device__ __forceinline__ void compose(float* C, const float* P, const float* A) {
#pragma unroll
    for (int j = 0; j < 4; j++) {
#pragma unroll
        for (int r = 0; r < 3; r++) {
            float v = fmaf(P[r], A[3 * j],
                      fmaf(P[3 + r], A[3 * j + 1], P[6 + r] * A[3 * j + 2]));
            if (j == 3) v += P[9 + r];
            C[3 * j + r] = v;
        }
    }
}

__global__ void __launch_bounds__(THREADS, 1)
a2b_kernel(const float* __restrict__ inp, const int* __restrict__ alen32,
           float* __restrict__ out, int L, int B) {
    const int b    = blockIdx.x;
    const int tid  = threadIdx.x;
    const int lane = tid & 31;
    const int wid  = tid >> 5;
    const int L3   = 3 * L;
    const int r0   = tid * RESID;
    const int t0   = tid * STEPS;

    // ---- dtype auto-detect for angles_length (int32 vs int64) ----
    // int64 with values in [1, 2^31): odd 32-bit words are all zero.
    // int32 with values >= 1: odd entries are nonzero. Check a few.
    bool is64 = true;
    {
        int nchk = (B < 4) ? B : 4;
        for (int k = 0; k < nchk; k++)
            if (alen32[2 * k + 1] != 0) { is64 = false; break; }
    }
    long long lenll = is64 ? ((const long long*)alen32)[b] : (long long)alen32[b];
    int tvalid = 3 * (int)lenll;
    if (tvalid > L3) tvalid = L3;
    if (tvalid < 0)  tvalid = 0;

    const bool anyValid  = (t0 < tvalid);
    const bool chunkFull = (t0 + STEPS <= tvalid);   // all 12 steps valid

    // bond-angle constants (compile-time foldable)
    const float CA0 = cosf(2.1186f), SA0 = sinf(2.1186f), RR0 = 1.33f;
    const float CA1 = cosf(1.9391f), SA1 = sinf(1.9391f), RR1 = 1.46f;
    const float CA2 = cosf(1.9111f), SA2 = sinf(1.9111f), RR2 = 1.525f;

    const float* phiRow = inp + (size_t)b * 2 * L;   // input[b,0,:]
    const float* psiRow = phiRow + L;                // input[b,1,:]
    float* outB = out + (size_t)b * 3 * (size_t)L3;  // 9L floats per batch
    const bool fullChunk = (t0 + STEPS <= L3);       // chunk inside array

    // ---- sincos (only where consumed) ----
    float cph[RESID], sph[RESID], cpv[RESID], spv[RESID];
    const bool allResid = (3 * (r0 + RESID - 1) < tvalid);   // all 4 consumed
    if (allResid) {
        // Vectorized: phi[r0..r0+3], psi[r0..r0+3] as float4 (r0 multiple of
        // 4, rows 16B-aligned); psi_prev shifts by one.
        float4 p0 = *(const float4*)(phiRow + r0);
        float4 q0 = *(const float4*)(psiRow + r0);
        float phiA[RESID] = {p0.x, p0.y, p0.z, p0.w};
        float psvA[RESID];
        psvA[0] = (r0 >= 1) ? psiRow[r0 - 1] : 0.f;
        psvA[1] = q0.x; psvA[2] = q0.y; psvA[3] = q0.z;
#pragma unroll
        for (int i = 0; i < RESID; i++) {
            sincos_fast(phiA[i], sph[i], cph[i]);
            sincos_fast(psvA[i], spv[i], cpv[i]);
        }
    } else {
#pragma unroll
        for (int i = 0; i < RESID; i++) {
            int r = r0 + i;
            if (3 * r < tvalid) {        // residue contributes >= 1 step
                float phi = phiRow[r];
                float psv = (r >= 1) ? psiRow[r - 1] : 0.f;   // psi_prev
                sincos_fast(phi, sph[i], cph[i]);
                sincos_fast(psv, spv[i], cpv[i]);
            } else {
                cph[i] = 1.f; sph[i] = 0.f; cpv[i] = 1.f; spv[i] = 0.f;
            }
        }
    }

    // ---- phase 1: chunk product; record per-step local translations tau ----
    // After applying chunk matrices 1..s, A.trans == tau_s. pos[t0+s] =
    // R_prefix * tau_s + t_prefix, so phase 3 needs no matrix replay.
    float A[12];
    float tx[STEPS], ty[STEPS], tz[STEPS];
    if (chunkFull) {
        // Fast path: no per-step guards. First step: A = M directly
        // (A stays identity for tid==0, whose t=0 matrix is identity).
        if (t0 > 0) set_from_M(A, CA0, SA0, RR0, cpv[0], spv[0]);
        else        set_identity(A);
        tx[0] = A[9]; ty[0] = A[10]; tz[0] = A[11];
        stepmul_omega(A, CA1, SA1, RR1);
        tx[1] = A[9]; ty[1] = A[10]; tz[1] = A[11];
        stepmul(A, CA2, SA2, RR2, cph[0], sph[0]);
        tx[2] = A[9]; ty[2] = A[10]; tz[2] = A[11];
#pragma unroll
        for (int i = 1; i < RESID; i++) {
            stepmul(A, CA0, SA0, RR0, cpv[i], spv[i]);
            tx[3*i+0] = A[9]; ty[3*i+0] = A[10]; tz[3*i+0] = A[11];
            stepmul_omega(A, CA1, SA1, RR1);
            tx[3*i+1] = A[9]; ty[3*i+1] = A[10]; tz[3*i+1] = A[11];
            stepmul(A, CA2, SA2, RR2, cph[i], sph[i]);
            tx[3*i+2] = A[9]; ty[3*i+2] = A[10]; tz[3*i+2] = A[11];
        }
    } else if (anyValid) {
        // Boundary thread: per-step guards (rare; one warp per block).
        set_identity(A);
#pragma unroll
        for (int i = 0; i < RESID; i++) {
            int tb = t0 + 3 * i;
            if (tb > 0 && tb < tvalid)     // t==0 is the identity matrix
                stepmul(A, CA0, SA0, RR0, cpv[i], spv[i]);
            tx[3*i+0] = A[9]; ty[3*i+0] = A[10]; tz[3*i+0] = A[11];
            if (tb + 1 < tvalid)
                stepmul_omega(A, CA1, SA1, RR1);
            tx[3*i+1] = A[9]; ty[3*i+1] = A[10]; tz[3*i+1] = A[11];
            if (tb + 2 < tvalid)
                stepmul(A, CA2, SA2, RR2, cph[i], sph[i]);
            tx[3*i+2] = A[9]; ty[3*i+2] = A[10]; tz[3*i+2] = A[11];
        }
    } else {
        set_identity(A);
        // ---- phase 1.5: zero-fill NOW; stores overlap with the scan below.
        // (d_out is poisoned to 0xAA, so every element must be written.)
        if (fullChunk) {
            float4* dst = (float4*)(outB + (size_t)t0 * 3);
            float4 z = make_float4(0.f, 0.f, 0.f, 0.f);
#pragma unroll
            for (int q = 0; q < (STEPS * 3) / 4; q++) dst[q] = z;
        } else {
            for (int t = t0; t < L3; t++) {
                outB[(size_t)t * 3 + 0] = 0.f;
                outB[(size_t)t * 3 + 1] = 0.f;
                outB[(size_t)t * 3 + 2] = 0.f;
            }
        }
    }

    // ---- phase 2a: intra-warp inclusive scan (shuffles, no smem) ----
    // Skipped entirely (warp-uniform) when no lane in the warp has valid work:
    // such a warp's totals/prefixes are never consumed by a valid thread
    // (validity is a tid-prefix), and its wtot entry stays identity.
    float Ein[12];
    set_identity(Ein);
    const bool warpActive = __any_sync(0xffffffffu, anyValid);
    if (warpActive) {
#pragma unroll
        for (int d = 1; d < 32; d <<= 1) {
            float Pm[12];
#pragma unroll
            for (int k = 0; k < 12; k++)
                Pm[k] = __shfl_up_sync(0xffffffffu, A[k], d);
            float C[12];
            compose(C, Pm, A);
            if (lane >= d) {
#pragma unroll
                for (int k = 0; k < 12; k++) A[k] = C[k];
            }
        }
        // intra-warp EXCLUSIVE prefix (capture before A is consumed)
#pragma unroll
        for (int k = 0; k < 12; k++)
            Ein[k] = __shfl_up_sync(0xffffffffu, A[k], 1);
        if (lane == 0) set_identity(Ein);
    }

    // ---- phase 2b: publish warp totals; ONE barrier; every active warp
    // redundantly scans the 16 totals in its own lanes (parallel across
    // warps -- no warp-0 serialization, no second barrier). ----
    __shared__ float wtot[NWARPS][12];
    if (lane == 31) {
#pragma unroll
        for (int k = 0; k < 12; k++) wtot[wid][k] = A[k];   // identity if idle
    }
    __syncthreads();

    // Fully-idle warps are done (zeros already written; no barriers follow).
    if (!warpActive) return;

    {
        float T[12];
        if (lane < NWARPS) {
#pragma unroll
            for (int k = 0; k < 12; k++) T[k] = wtot[lane][k];
        } else {
            set_identity(T);
        }
#pragma unroll
        for (int d = 1; d < NWARPS; d <<= 1) {
            float Pm[12];
#pragma unroll
            for (int k = 0; k < 12; k++)
                Pm[k] = __shfl_up_sync(0xffffffffu, T[k], d);
            float C[12];
            compose(C, Pm, T);
            if (lane >= d && lane < NWARPS) {
#pragma unroll
                for (int k = 0; k < 12; k++) T[k] = C[k];
            }
        }
        // This warp's exclusive cross-warp prefix = inclusive[wid-1].
        float W[12];
        int src = (wid > 0) ? (wid - 1) : 0;
#pragma unroll
        for (int k = 0; k < 12; k++)
            W[k] = __shfl_sync(0xffffffffu, T[k], src);
        if (wid == 0) set_identity(W);

        // thread's global exclusive prefix = W * intra-warp exclusive
        float C[12];
        compose(C, W, Ein);
#pragma unroll
        for (int k = 0; k < 12; k++) A[k] = C[k];
    }

    // ---- phase 3 (boundary-warp tail lanes exit only now, after all
    // warp-collective ops) ----
    if (!anyValid) return;

    // pos[t0+s] = R_prefix * tau_s + t_prefix  (9 FMA per step; no replay)
    float buf[12];
#pragma unroll
    for (int s = 0; s < STEPS; s++) {
        bool v = (t0 + s < tvalid);
        float px = fmaf(A[0], tx[s], fmaf(A[3], ty[s], fmaf(A[6], tz[s], A[9])));
        float py = fmaf(A[1], tx[s], fmaf(A[4], ty[s], fmaf(A[7], tz[s], A[10])));
        float pz = fmaf(A[2], tx[s], fmaf(A[5], ty[s], fmaf(A[8], tz[s], A[11])));
        buf[(s & 3) * 3 + 0] = v ? px : 0.f;
        buf[(s & 3) * 3 + 1] = v ? py : 0.f;
        buf[(s & 3) * 3 + 2] = v ? pz : 0.f;
        if ((s & 3) == 3) {
            size_t off = (size_t)(t0 + s - 3) * 3;
            if (fullChunk) {
                float4* dst = (float4*)(outB + off);
                dst[0] = make_float4(buf[0], buf[1], buf[2],  buf[3]);
                dst[1] = make_float4(buf[4], buf[5], buf[6],  buf[7]);
                dst[2] = make_float4(buf[8], buf[9], buf[10], buf[11]);
            } else {
#pragma unroll
                for (int m = 0; m < 12; m++) {
                    int t2 = t0 + (s - 3) + m / 3;
                    if (t2 < L3) outB[off + m] = buf[m];
                }
            }
        }
    }
}

extern "C" void kernel_launch(void* const* d_in, const int* in_sizes, int n_in,
                              void* d_out, int out_size) {
    const float* inp  = (const float*)d_in[0];   // [B,2,L] f32
    const int*   alen = (const int*)d_in[1];     // [B] i32 or i64 (detected)
    float*       out  = (float*)d_out;           // [B,9L] f32

    int B = in_sizes[1];
    int L = in_sizes[0] / (2 * B);

    a2b_kernel<<<B, THREADS>>>(inp, alen, out, L, B);
}